// round 1
// baseline (speedup 1.0000x reference)
#include <cuda_runtime.h>
#include <math.h>

// Problem constants (fixed by setup_inputs): flows [4,32,2,128,128], images [4,32,32,128,128]
#define Bc 4
#define Lc 32
#define Cc 32
#define Hc 128
#define Wc 128
#define HWc (Hc*Wc)

// Scratch: ping-pong buffers for non-finalized slices. Finalized image slices go
// straight to d_out; finalized flow slices go to g_flowF.
__device__ float g_imgA[(size_t)Bc*Lc*Cc*HWc];   // 256 MB
__device__ float g_imgB[(size_t)Bc*Lc*Cc*HWc];   // 256 MB
__device__ float g_flowA[(size_t)Bc*Lc*2*HWc];   // 16 MB
__device__ float g_flowB[(size_t)Bc*Lc*2*HWc];   // 16 MB
__device__ float g_flowF[(size_t)Bc*Lc*2*HWc];   // 16 MB

__global__ void copy_slice0(const float* __restrict__ img, float* __restrict__ out) {
    int i = blockIdx.x * blockDim.x + threadIdx.x;
    const int per = Cc * HWc / 4;            // float4 per (b, l=0) slice
    const int n = Bc * per;
    if (i >= n) return;
    int b = i / per, r = i % per;
    const float4* s = (const float4*)(img + (size_t)b * Lc * Cc * HWc) + r;
    float4* d = (float4*)(out + (size_t)b * Lc * Cc * HWc) + r;
    *d = *s;
}

__global__ void compose_step(
    int step,
    const float* __restrict__ srcImg,  const float* __restrict__ inImg,
    float* __restrict__ finImg,        float* __restrict__ dstImg,
    const float* __restrict__ srcFlow, const float* __restrict__ inFlow,
    float* __restrict__ finFlow,       float* __restrict__ dstFlow)
{
    const int Lp = Lc - step;
    long long idx = (long long)blockIdx.x * blockDim.x + threadIdx.x;
    long long total = (long long)Bc * Lp * HWc;
    if (idx >= total) return;

    int pix  = (int)(idx % HWc);
    int rest = (int)(idx / HWc);
    int li   = rest % Lp;          // = lp (prev slice index)
    int b    = rest / Lp;
    int l    = step + li;          // curr/output slice index
    int lp   = li;
    int h = pix >> 7;              // / Wc
    int w = pix & (Wc - 1);

    // --- current (q) flow values ---
    const float* cf = srcFlow + (size_t)(b * Lc + l) * 2 * HWc;
    float qfx = __ldg(cf + pix);
    float qfy = __ldg(cf + HWc + pix);

    // --- grid generation (matches reference exactly) ---
    float gx = -1.0f + (2.0f / Wc) * ((float)w + 0.5f);
    float gy = -1.0f + (2.0f / Hc) * ((float)h + 0.5f);
    float fx = gx + qfx;
    float t  = fx + 1.0f;
    fx = t - 2.0f * floorf(t * 0.5f) - 1.0f;   // jnp.remainder(fx+1, 2) - 1
    float fy = gy + qfy;

    float x = (fx + 1.0f) * (Wc * 0.5f) - 0.5f;
    float y = (fy + 1.0f) * (Hc * 0.5f) - 0.5f;
    float x0f = floorf(x), y0f = floorf(y);
    float tx = x - x0f, ty = y - y0f;
    int x0 = (int)x0f, y0 = (int)y0f;
    int x1 = x0 + 1,  y1 = y0 + 1;

    float vx0 = (x0 >= 0 && x0 < Wc) ? 1.0f : 0.0f;
    float vx1 = (x1 >= 0 && x1 < Wc) ? 1.0f : 0.0f;
    float vy0 = (y0 >= 0 && y0 < Hc) ? 1.0f : 0.0f;
    float vy1 = (y1 >= 0 && y1 < Hc) ? 1.0f : 0.0f;

    float w00 = (1.0f - tx) * (1.0f - ty) * vx0 * vy0;
    float w01 = tx * (1.0f - ty) * vx1 * vy0;
    float w10 = (1.0f - tx) * ty * vx0 * vy1;
    float w11 = tx * ty * vx1 * vy1;

    int cx0 = min(max(x0, 0), Wc - 1), cx1 = min(max(x1, 0), Wc - 1);
    int cy0 = min(max(y0, 0), Hc - 1), cy1 = min(max(y1, 0), Hc - 1);
    int o00 = cy0 * Wc + cx0, o01 = cy0 * Wc + cx1;
    int o10 = cy1 * Wc + cx0, o11 = cy1 * Wc + cx1;

    // --- source selection (warp-uniform per (b,l)) ---
    // prev slice lp: 0 -> original input; [1,step) -> finalized; >=step -> scratch (== srcImg/srcFlow)
    const float* pf = (lp == 0) ? (inFlow + (size_t)(b * Lc) * 2 * HWc)
                   : (lp < step) ? (finFlow + (size_t)(b * Lc + lp) * 2 * HWc)
                                 : (srcFlow + (size_t)(b * Lc + lp) * 2 * HWc);
    float* df = ((l < 2 * step) ? finFlow : dstFlow) + (size_t)(b * Lc + l) * 2 * HWc;

    {
        float s0 = w00 * __ldg(pf + o00) + w01 * __ldg(pf + o01)
                 + w10 * __ldg(pf + o10) + w11 * __ldg(pf + o11);
        const float* pf1 = pf + HWc;
        float s1 = w00 * __ldg(pf1 + o00) + w01 * __ldg(pf1 + o01)
                 + w10 * __ldg(pf1 + o10) + w11 * __ldg(pf1 + o11);
        df[pix]       = qfx + s0;
        df[HWc + pix] = qfy + s1;
    }

    const float* ci  = srcImg + (size_t)(b * Lc + l) * Cc * HWc + pix;
    const float* piB = ((lp == 0) ? inImg : (lp < step) ? finImg : srcImg)
                       + (size_t)(b * Lc + lp) * Cc * HWc;
    float* di = ((l < 2 * step) ? finImg : dstImg) + (size_t)(b * Lc + l) * Cc * HWc + pix;

    #pragma unroll 8
    for (int c = 0; c < Cc; c++) {
        const float* p = piB + c * HWc;
        float sv = w00 * __ldg(p + o00) + w01 * __ldg(p + o01)
                 + w10 * __ldg(p + o10) + w11 * __ldg(p + o11);
        di[c * HWc] = __ldg(ci + c * HWc) + sv;
    }
}

extern "C" void kernel_launch(void* const* d_in, const int* in_sizes, int n_in,
                              void* d_out, int out_size) {
    const float* flows  = (const float*)d_in[0];
    const float* images = (const float*)d_in[1];
    if (n_in >= 2 && in_sizes[0] > in_sizes[1]) {   // robustness: flows is the smaller input
        const float* tmp = flows; flows = images; images = tmp;
    }
    float* out = (float*)d_out;

    float *iA, *iB, *fA, *fB, *fF;
    cudaGetSymbolAddress((void**)&iA, g_imgA);
    cudaGetSymbolAddress((void**)&iB, g_imgB);
    cudaGetSymbolAddress((void**)&fA, g_flowA);
    cudaGetSymbolAddress((void**)&fB, g_flowB);
    cudaGetSymbolAddress((void**)&fF, g_flowF);

    // slice 0 of output == input images slice 0
    {
        int n = Bc * Cc * HWc / 4;
        copy_slice0<<<(n + 255) / 256, 256>>>(images, out);
    }

    float* imgScr[2]  = {iA, iB};
    float* flowScr[2] = {fA, fB};
    const float* sImg  = images;
    const float* sFlow = flows;
    int d = 0;
    for (int s = 1; s < Lc; s <<= 1) {
        long long total = (long long)Bc * (Lc - s) * HWc;
        int blocks = (int)((total + 255) / 256);
        compose_step<<<blocks, 256>>>(s,
                                      sImg, images, out, imgScr[d],
                                      sFlow, flows, fF, flowScr[d]);
        sImg = imgScr[d];
        sFlow = flowScr[d];
        d ^= 1;
    }
}

// round 2
// speedup vs baseline: 1.4430x; 1.4430x over previous
#include <cuda_runtime.h>
#include <math.h>

// Problem constants: flows [4,32,2,128,128], images [4,32,32,128,128], fp32
#define Bc 4
#define Lc 32
#define Cc 32
#define Hc 128
#define Wc 128
#define HWc (Hc*Wc)
#define IMG_SLICE (Cc*HWc)

// Internal image buffers in channel-interleaved [B,L,H,W,C] layout.
// iA: transposed input (slice 0 preserved for lp==0 reads), iB: ping-pong, iF: finalized.
__device__ float g_imgA[(size_t)Bc*Lc*IMG_SLICE];   // 256 MB
__device__ float g_imgB[(size_t)Bc*Lc*IMG_SLICE];   // 256 MB
__device__ float g_imgF[(size_t)Bc*Lc*IMG_SLICE];   // 256 MB
// Flow buffers stay planar [B,L,2,H,W]
__device__ float g_flowA[(size_t)Bc*Lc*2*HWc];      // 16 MB
__device__ float g_flowB[(size_t)Bc*Lc*2*HWc];      // 16 MB
__device__ float g_flowF[(size_t)Bc*Lc*2*HWc];      // 16 MB

// ---------------------------------------------------------------------------
// CHW -> HWC transpose, all B*L slices. Block = 256 threads, tile = 64 pix x 32 ch.
__global__ void t_chw2hwc(const float* __restrict__ src, float* __restrict__ dst) {
    __shared__ float sm[32][65];
    int tile = blockIdx.x & 255;            // HW/64 = 256 tiles per slice
    int sl   = blockIdx.x >> 8;             // 0..B*L-1
    int pix0 = tile * 64;
    const float* s = src + (size_t)sl * IMG_SLICE;
    float*       d = dst + (size_t)sl * IMG_SLICE;
    int tx = threadIdx.x & 63, ty = threadIdx.x >> 6;   // 64 x 4
    #pragma unroll
    for (int i = 0; i < 8; i++) {
        int c = ty + i * 4;
        sm[c][tx] = s[c * HWc + pix0 + tx];
    }
    __syncthreads();
    #pragma unroll
    for (int j = 0; j < 2; j++) {
        int u = threadIdx.x + j * 256;
        int p = u >> 3, q = u & 7;
        float4 v = make_float4(sm[4*q+0][p], sm[4*q+1][p], sm[4*q+2][p], sm[4*q+3][p]);
        *(float4*)(d + (size_t)(pix0 + p) * Cc + 4 * q) = v;
    }
}

// HWC finalized buffer -> CHW d_out, slices l=1..31 only.
__global__ void t_hwc2chw_fin(const float* __restrict__ srcF, float* __restrict__ out) {
    __shared__ float sm[32][65];
    int tile = blockIdx.x & 255;
    int sl   = blockIdx.x >> 8;             // 0..4*31-1
    int l = 1 + (sl % 31);
    int b = sl / 31;
    size_t base = (size_t)(b * Lc + l) * IMG_SLICE;
    int pix0 = tile * 64;
    int tx = threadIdx.x & 63, ty = threadIdx.x >> 6;
    #pragma unroll
    for (int j = 0; j < 2; j++) {
        int u = threadIdx.x + j * 256;
        int p = u >> 3, q = u & 7;
        float4 v = *(const float4*)(srcF + base + (size_t)(pix0 + p) * Cc + 4 * q);
        sm[4*q+0][p] = v.x; sm[4*q+1][p] = v.y; sm[4*q+2][p] = v.z; sm[4*q+3][p] = v.w;
    }
    __syncthreads();
    #pragma unroll
    for (int i = 0; i < 8; i++) {
        int c = ty + i * 4;
        out[base + c * HWc + pix0 + tx] = sm[c][tx];
    }
}

// Output slice 0 = input images slice 0 (straight CHW copy).
__global__ void copy_slice0(const float* __restrict__ img, float* __restrict__ out) {
    int i = blockIdx.x * blockDim.x + threadIdx.x;
    const int per = IMG_SLICE / 4;
    const int n = Bc * per;
    if (i >= n) return;
    int b = i / per, r = i % per;
    const float4* s = (const float4*)(img + (size_t)b * Lc * IMG_SLICE) + r;
    float4*       d = (float4*)(out + (size_t)b * Lc * IMG_SLICE) + r;
    *d = *s;
}

// ---------------------------------------------------------------------------
// Shared grid/weight computation (matches reference exactly)
__device__ __forceinline__ void grid_weights(
    int pix, float qfx, float qfy,
    float& w00, float& w01, float& w10, float& w11,
    int& o00, int& o01, int& o10, int& o11)
{
    int h = pix >> 7;
    int w = pix & (Wc - 1);
    float gx = -1.0f + (2.0f / Wc) * ((float)w + 0.5f);
    float gy = -1.0f + (2.0f / Hc) * ((float)h + 0.5f);
    float fx = gx + qfx;
    float t  = fx + 1.0f;
    fx = t - 2.0f * floorf(t * 0.5f) - 1.0f;   // remainder(fx+1,2)-1 (x wrap)
    float fy = gy + qfy;

    float x = (fx + 1.0f) * (Wc * 0.5f) - 0.5f;
    float y = (fy + 1.0f) * (Hc * 0.5f) - 0.5f;
    float x0f = floorf(x), y0f = floorf(y);
    float tx = x - x0f, ty = y - y0f;
    int x0 = (int)x0f, y0 = (int)y0f;
    int x1 = x0 + 1,  y1 = y0 + 1;

    float vx0 = (x0 >= 0 && x0 < Wc) ? 1.0f : 0.0f;
    float vx1 = (x1 >= 0 && x1 < Wc) ? 1.0f : 0.0f;
    float vy0 = (y0 >= 0 && y0 < Hc) ? 1.0f : 0.0f;
    float vy1 = (y1 >= 0 && y1 < Hc) ? 1.0f : 0.0f;

    w00 = (1.0f - tx) * (1.0f - ty) * vx0 * vy0;
    w01 = tx * (1.0f - ty) * vx1 * vy0;
    w10 = (1.0f - tx) * ty * vx0 * vy1;
    w11 = tx * ty * vx1 * vy1;

    int cx0 = min(max(x0, 0), Wc - 1), cx1 = min(max(x1, 0), Wc - 1);
    int cy0 = min(max(y0, 0), Hc - 1), cy1 = min(max(y1, 0), Hc - 1);
    o00 = cy0 * Wc + cx0; o01 = cy0 * Wc + cx1;
    o10 = cy1 * Wc + cx0; o11 = cy1 * Wc + cx1;
}

// ---------------------------------------------------------------------------
// Flow compose (planar layout). One thread per output pixel, handles both channels.
__global__ void compose_flow(int step,
    const float* __restrict__ srcFlow, const float* __restrict__ orgFlow,
    float* __restrict__ finFlow, float* __restrict__ dstFlow)
{
    const int Lp = Lc - step;
    int idx = blockIdx.x * blockDim.x + threadIdx.x;
    int total = Bc * Lp * HWc;
    if (idx >= total) return;
    int pix  = idx % HWc;
    int rest = idx / HWc;
    int lp   = rest % Lp;
    int b    = rest / Lp;
    int l    = step + lp;

    const float* cf = srcFlow + (size_t)(b * Lc + l) * 2 * HWc;
    float qfx = __ldg(cf + pix);
    float qfy = __ldg(cf + HWc + pix);

    float w00, w01, w10, w11; int o00, o01, o10, o11;
    grid_weights(pix, qfx, qfy, w00, w01, w10, w11, o00, o01, o10, o11);

    const float* pf = (lp == 0) ? (orgFlow + (size_t)(b * Lc) * 2 * HWc)
                   : (lp < step) ? (finFlow + (size_t)(b * Lc + lp) * 2 * HWc)
                                 : (srcFlow + (size_t)(b * Lc + lp) * 2 * HWc);
    float* df = ((l < 2 * step) ? finFlow : dstFlow) + (size_t)(b * Lc + l) * 2 * HWc;

    float s0 = w00 * __ldg(pf + o00) + w01 * __ldg(pf + o01)
             + w10 * __ldg(pf + o10) + w11 * __ldg(pf + o11);
    const float* pf1 = pf + HWc;
    float s1 = w00 * __ldg(pf1 + o00) + w01 * __ldg(pf1 + o01)
             + w10 * __ldg(pf1 + o10) + w11 * __ldg(pf1 + o11);
    df[pix]       = qfx + s0;
    df[HWc + pix] = qfy + s1;
}

// ---------------------------------------------------------------------------
// Image compose in HWC layout. Thread = (pixel, group of 4 channels).
// Warp = 4 consecutive pixels x 8 channel-groups -> every tap is a 128B-aligned
// contiguous 128B line per pixel (1 wavefront), float4 loads/stores throughout.
__global__ void compose_img(int step,
    const float* __restrict__ srcImg, const float* __restrict__ orgImg,
    float* __restrict__ finImg,       float* __restrict__ dstImg,
    const float* __restrict__ srcFlow)
{
    const int Lp = Lc - step;
    long long id = (long long)blockIdx.x * blockDim.x + threadIdx.x;
    long long total = (long long)Bc * Lp * HWc * 8;
    if (id >= total) return;

    int c4 = (int)(id & 7);
    long long pixIdx = id >> 3;
    int pix  = (int)(pixIdx % HWc);
    int rest = (int)(pixIdx / HWc);
    int lp   = rest % Lp;
    int b    = rest / Lp;
    int l    = step + lp;

    // curr flow (slice l, always in srcFlow since l >= step); broadcast across 8 lanes
    const float* cf = srcFlow + (size_t)(b * Lc + l) * 2 * HWc;
    float qfx = __ldg(cf + pix);
    float qfy = __ldg(cf + HWc + pix);

    float w00, w01, w10, w11; int o00, o01, o10, o11;
    grid_weights(pix, qfx, qfy, w00, w01, w10, w11, o00, o01, o10, o11);

    const float* pi = ((lp == 0) ? orgImg : (lp < step) ? finImg : srcImg)
                      + (size_t)(b * Lc + lp) * IMG_SLICE;
    int co = c4 * 4;

    float4 t00 = __ldg((const float4*)(pi + (size_t)o00 * Cc + co));
    float4 t01 = __ldg((const float4*)(pi + (size_t)o01 * Cc + co));
    float4 t10 = __ldg((const float4*)(pi + (size_t)o10 * Cc + co));
    float4 t11 = __ldg((const float4*)(pi + (size_t)o11 * Cc + co));

    size_t coff = (size_t)(b * Lc + l) * IMG_SLICE + (size_t)pix * Cc + co;
    float4 cv = __ldg((const float4*)(srcImg + coff));

    float4 r;
    r.x = cv.x + w00 * t00.x + w01 * t01.x + w10 * t10.x + w11 * t11.x;
    r.y = cv.y + w00 * t00.y + w01 * t01.y + w10 * t10.y + w11 * t11.y;
    r.z = cv.z + w00 * t00.z + w01 * t01.z + w10 * t10.z + w11 * t11.z;
    r.w = cv.w + w00 * t00.w + w01 * t01.w + w10 * t10.w + w11 * t11.w;

    float* di = (l < 2 * step) ? finImg : dstImg;
    *(float4*)(di + coff) = r;
}

// ---------------------------------------------------------------------------
extern "C" void kernel_launch(void* const* d_in, const int* in_sizes, int n_in,
                              void* d_out, int out_size) {
    const float* flows  = (const float*)d_in[0];
    const float* images = (const float*)d_in[1];
    if (n_in >= 2 && in_sizes[0] > in_sizes[1]) {
        const float* tmp = flows; flows = images; images = tmp;
    }
    float* out = (float*)d_out;

    float *iA, *iB, *iF, *fA, *fB, *fF;
    cudaGetSymbolAddress((void**)&iA, g_imgA);
    cudaGetSymbolAddress((void**)&iB, g_imgB);
    cudaGetSymbolAddress((void**)&iF, g_imgF);
    cudaGetSymbolAddress((void**)&fA, g_flowA);
    cudaGetSymbolAddress((void**)&fB, g_flowB);
    cudaGetSymbolAddress((void**)&fF, g_flowF);

    // 1) transpose full input image tensor CHW -> HWC into iA
    t_chw2hwc<<<Bc * Lc * 256, 256>>>(images, iA);

    // 2) output slice 0 = input slice 0
    {
        int n = Bc * IMG_SLICE / 4;
        copy_slice0<<<(n + 255) / 256, 256>>>(images, out);
    }

    // 3) log-scan. Images ping-pong iA<->iB (iA slice 0 only ever read);
    //    flows ping-pong: input -> fB -> fA -> fB -> fA.
    const float* sImg  = iA;  float* dImg  = iB;
    const float* sFlow = flows; float* dFlow = fB;
    for (int s = 1; s < Lc; s <<= 1) {
        long long pixT = (long long)Bc * (Lc - s) * HWc;

        if (s < 16) {   // last step's flow output never consumed
            int blocks = (int)((pixT + 255) / 256);
            compose_flow<<<blocks, 256>>>(s, sFlow, flows, fF, dFlow);
        }
        {
            long long tot = pixT * 8;
            int blocks = (int)((tot + 255) / 256);
            compose_img<<<blocks, 256>>>(s, sImg, iA, iF, dImg, sFlow);
        }
        // swap
        const float* tI = sImg; sImg = dImg; dImg = (float*)tI;
        if (dImg == (float*)iA) { /* ok: step writes only l>=2s>=4, slice0 safe */ }
        if (s == 1) { sFlow = fB; dFlow = fA; }
        else { const float* tF = sFlow; sFlow = dFlow; dFlow = (float*)tF; }
    }

    // 4) finalized slices 1..31: HWC -> CHW into d_out
    t_hwc2chw_fin<<<Bc * 31 * 256, 256>>>(iF, out);
}